// round 7
// baseline (speedup 1.0000x reference)
#include <cuda_runtime.h>

#define D_IN   187
#define H_HID  50
#define C_OUT  5
#define LPR    8            // lanes per row
#define HP     7            // h per lane (8*7=56, h>=50 zero-padded)
#define TPB    128
#define RPB    (TPB/LPR)    // 16 rows per block
#define DCH    94           // d-chunk (2 chunks: 94 + 93)
#define THR    1.0f
#define BETA   0.9f

// Shared layout (floats):
//  sW1: [j][dloc][8]  addr = j*756 + dloc*8 + i   (i<7 used; j-pitch 756:
//       756 mod 32 = 20 -> 8 lanes hit distinct banks; 16B-aligned for float4)
//  sW2: [h][8]  (h padded to 56)
//  sx : [r][DCH]
#define W1_JP   756
#define SM_W1   0
#define SM_W1_SZ (LPR * W1_JP)           // 6048
#define SM_W2   (SM_W1 + SM_W1_SZ)
#define SM_W2_SZ (56 * 8)                // 448
#define SM_X    (SM_W2 + SM_W2_SZ)
#define SM_X_SZ (RPB * DCH)              // 1504
#define SMEM_BYTES ((SM_X + SM_X_SZ) * 4)   // 32000 B

__global__ __launch_bounds__(TPB, 6)
void snn_fused_kernel(const float* __restrict__ x,
                      const float* __restrict__ W1,
                      const float* __restrict__ b1,
                      const float* __restrict__ W2,
                      const float* __restrict__ b2,
                      float* __restrict__ out,
                      int B, int steps)
{
    extern __shared__ float smem[];
    float* sW1 = smem + SM_W1;
    float* sW2 = smem + SM_W2;
    float* sx  = smem + SM_X;

    const int tid   = threadIdx.x;
    const int j     = tid & (LPR - 1);
    const int rloc  = tid >> 3;
    const int row   = blockIdx.x * RPB + rloc;
    const bool rowv = (row < B);
    const int hbase = j * HP;

    // ---- stage W2 [h][8], h>=50 zero ----
    for (int idx = tid; idx < 56 * C_OUT; idx += TPB) {
        int h = idx % 56, c = idx / 56;
        sW2[h * 8 + c] = (h < H_HID) ? W2[c * H_HID + h] : 0.0f;
    }

    // ---- phase 1: cur1 via exact ascending-k fma chain, d in 2 chunks ----
    float cur1[HP];
#pragma unroll
    for (int i = 0; i < HP; ++i) cur1[i] = 0.0f;

    for (int d0 = 0; d0 < D_IN; d0 += DCH) {
        const int len = (D_IN - d0 < DCH) ? (D_IN - d0) : DCH;
        __syncthreads();
        // stage W1 chunk: [h][d] -> sW1[(h/7)*756 + dloc*8 + h%7]
        for (int idx = tid; idx < 56 * len; idx += TPB) {
            int h = idx % 56, dloc = idx / 56;
            float v = (h < H_HID) ? W1[h * D_IN + d0 + dloc] : 0.0f;
            sW1[(h / HP) * W1_JP + dloc * 8 + (h % HP)] = v;
        }
        // stage x chunk
        for (int i2 = tid; i2 < RPB * len; i2 += TPB) {
            int r  = i2 / len;
            int dl = i2 - r * len;
            int gr = blockIdx.x * RPB + r;
            sx[r * DCH + dl] = (gr < B) ? x[(size_t)gr * D_IN + d0 + dl] : 0.0f;
        }
        __syncthreads();
        const float* wbase = &sW1[j * W1_JP];
        const float* xbase = &sx[rloc * DCH];
        for (int dl = 0; dl < len; ++dl) {
            const float xv = xbase[dl];
            const float* wp = wbase + dl * 8;
            float4 wa = *(const float4*)(wp);
            float2 wb = *(const float2*)(wp + 4);
            float  wc = wp[6];
            cur1[0] = fmaf(wa.x, xv, cur1[0]);
            cur1[1] = fmaf(wa.y, xv, cur1[1]);
            cur1[2] = fmaf(wa.z, xv, cur1[2]);
            cur1[3] = fmaf(wa.w, xv, cur1[3]);
            cur1[4] = fmaf(wb.x, xv, cur1[4]);
            cur1[5] = fmaf(wb.y, xv, cur1[5]);
            cur1[6] = fmaf(wc,   xv, cur1[6]);
        }
    }
    // bias: separate rounded add (reference epilogue); pad h -> 0
#pragma unroll
    for (int i = 0; i < HP; ++i) {
        int h = hbase + i;
        cur1[i] = (h < H_HID) ? __fadd_rn(cur1[i], b1[h]) : 0.0f;
    }

    // ---- W2 columns register-resident (35 regs) ----
    float w2r[HP][C_OUT];
#pragma unroll
    for (int i = 0; i < HP; ++i) {
        float4 a = *(const float4*)&sW2[(hbase + i) * 8];
        w2r[i][0] = a.x; w2r[i][1] = a.y; w2r[i][2] = a.z; w2r[i][3] = a.w;
        w2r[i][4] = sW2[(hbase + i) * 8 + 4];
    }

    // ---- phase 2: 8-deep time-skewed relay (lane j handles t = i - j) ----
    // cur2's 50-term chain stays exactly serial: lane j continues the fma
    // chain from lane j-1's partial (shfl). Pad h never spikes (cur1=0,
    // w2=0) -> exact no-ops. Inner form identical to R5: FSEL + r-as-
    // multiplier FMA (keeps accumulates on the fma pipe).
    float mem1[HP];
    float r1[HP];
#pragma unroll
    for (int i = 0; i < HP; ++i) { mem1[i] = 0.0f; r1[i] = 0.0f; }

    float P[C_OUT] = {0, 0, 0, 0, 0};
    float mem2[C_OUT], rb2[C_OUT];
#pragma unroll
    for (int c = 0; c < C_OUT; ++c) { mem2[c] = 0.0f; rb2[c] = b2[c]; }

    const size_t memoff = (size_t)steps * B * C_OUT;
    const int iters = steps + LPR - 1;
    const bool storer = (j == LPR - 1) && rowv;

    for (int i = 0; i < iters; ++i) {
        float cin[C_OUT];
#pragma unroll
        for (int c = 0; c < C_OUT; ++c)
            cin[c] = __shfl_up_sync(0xFFFFFFFFu, P[c], 1, LPR);

        const int t = i - j;
        // steady state covers i in [LPR-1, steps): every lane active
        const bool active = (unsigned)t < (unsigned)steps;
        if (active) {
            float a0 = (j == 0) ? 0.0f : cin[0];
            float a1 = (j == 0) ? 0.0f : cin[1];
            float a2 = (j == 0) ? 0.0f : cin[2];
            float a3 = (j == 0) ? 0.0f : cin[3];
            float a4 = (j == 0) ? 0.0f : cin[4];

#pragma unroll
            for (int hh = 0; hh < HP; ++hh) {
                float m = __fsub_rn(fmaf(BETA, mem1[hh], cur1[hh]), r1[hh]);
                mem1[hh] = m;
                const float s = (m > THR) ? 1.0f : 0.0f;
                r1[hh] = s;                      // spike(t) == reset(t+1)
                a0 = fmaf(s, w2r[hh][0], a0);
                a1 = fmaf(s, w2r[hh][1], a1);
                a2 = fmaf(s, w2r[hh][2], a2);
                a3 = fmaf(s, w2r[hh][3], a3);
                a4 = fmaf(s, w2r[hh][4], a4);
            }
            P[0] = a0; P[1] = a1; P[2] = a2; P[3] = a3; P[4] = a4;

            if (storer) {
                const size_t ob = (size_t)t * B * C_OUT + (size_t)row * C_OUT;
#pragma unroll
                for (int c = 0; c < C_OUT; ++c) {
                    const float cur2 = __fadd_rn(P[c], rb2[c]);   // dot + b2
                    float m2 = mem2[c];
                    const float r2 = (m2 > THR) ? 1.0f : 0.0f;
                    m2 = __fsub_rn(fmaf(BETA, m2, cur2), r2);
                    mem2[c] = m2;
                    out[ob + c]          = (m2 > THR) ? 1.0f : 0.0f;  // spk_rec
                    out[memoff + ob + c] = m2;                         // mem_rec
                }
            }
        }
    }
}

extern "C" void kernel_launch(void* const* d_in, const int* in_sizes, int n_in,
                              void* d_out, int out_size)
{
    const float* x  = (const float*)d_in[0];
    const float* W1 = (const float*)d_in[1];
    const float* b1 = (const float*)d_in[2];
    const float* W2 = (const float*)d_in[3];
    const float* b2 = (const float*)d_in[4];
    float* out = (float*)d_out;

    const int B = in_sizes[0] / D_IN;
    const int steps = (int)((long long)out_size / (2LL * B * C_OUT));

    cudaFuncSetAttribute(snn_fused_kernel,
                         cudaFuncAttributeMaxDynamicSharedMemorySize, SMEM_BYTES);

    const int grid = (B + RPB - 1) / RPB;
    snn_fused_kernel<<<grid, TPB, SMEM_BYTES>>>(x, W1, b1, W2, b2, out, B, steps);
}

// round 8
// speedup vs baseline: 1.4425x; 1.4425x over previous
#include <cuda_runtime.h>

#define D_IN   187
#define H_HID  50
#define C_OUT  5
#define LPR    4            // lanes per row
#define HP     13           // h per lane (52 padded)
#define TPB    128
#define RPB    (TPB/LPR)    // 32 rows per block
#define DCH    94           // d-chunk (2 chunks: 94 + 93)
#define THR    1.0f
#define BETA   0.9f

// Shared layout (floats):
//  sW1: [dloc][j*20+i]  pitch 80/d; lane bases {0,20,8,28} mod 32 -> conflict-free float4
//  sW2: [h][8] (h padded to 52)
//  sx : [r][DCH]  (r*94 mod 32 distinct across the 8 rows of a warp)
#define SM_W1   0
#define SM_W1_SZ (DCH * 80)              // 7520
#define SM_W2   (SM_W1 + SM_W1_SZ)
#define SM_W2_SZ (52 * 8)                // 416
#define SM_X    (SM_W2 + SM_W2_SZ)
#define SM_X_SZ (RPB * DCH)              // 3008
#define SMEM_BYTES ((SM_X + SM_X_SZ) * 4)   // 43776 B

__global__ __launch_bounds__(TPB, 4)
void snn_fused_kernel(const float* __restrict__ x,
                      const float* __restrict__ W1,
                      const float* __restrict__ b1,
                      const float* __restrict__ W2,
                      const float* __restrict__ b2,
                      float* __restrict__ out,
                      int B, int steps)
{
    extern __shared__ float smem[];
    float* sW1 = smem + SM_W1;
    float* sW2 = smem + SM_W2;
    float* sx  = smem + SM_X;

    const int tid   = threadIdx.x;
    const int j     = tid & (LPR - 1);
    const int rloc  = tid >> 2;
    const int row   = blockIdx.x * RPB + rloc;
    const bool rowv = (row < B);
    const int hbase = j * HP;

    // ---- stage W2 [h][8], h>=50 zero ----
    for (int idx = tid; idx < 52 * C_OUT; idx += TPB) {
        int h = idx % 52, c = idx / 52;
        sW2[h * 8 + c] = (h < H_HID) ? W2[c * H_HID + h] : 0.0f;
    }

    // ---- phase 1: cur1 via exact ascending-k fma chain; W1/x staged in 2 d-chunks ----
    float cur1[HP];
#pragma unroll
    for (int i = 0; i < HP; ++i) cur1[i] = 0.0f;

    for (int d0 = 0; d0 < D_IN; d0 += DCH) {
        const int len = (D_IN - d0 < DCH) ? (D_IN - d0) : DCH;
        __syncthreads();
        // stage W1 chunk: gmem [h][d] -> sW1[dloc*80 + (h/13)*20 + h%13]
        for (int idx = tid; idx < 52 * len; idx += TPB) {
            int h = idx % 52, dloc = idx / 52;
            float v = (h < H_HID) ? W1[h * D_IN + d0 + dloc] : 0.0f;
            sW1[dloc * 80 + (h / HP) * 20 + (h % HP)] = v;
        }
        // stage x chunk
        for (int i2 = tid; i2 < RPB * len; i2 += TPB) {
            int r  = i2 / len;
            int dl = i2 - r * len;
            int gr = blockIdx.x * RPB + r;
            sx[r * DCH + dl] = (gr < B) ? x[(size_t)gr * D_IN + d0 + dl] : 0.0f;
        }
        __syncthreads();
        const float* xbase = &sx[rloc * DCH];
        const float* wbase = &sW1[j * 20];
        for (int dl = 0; dl < len; ++dl) {
            const float xv = xbase[dl];
            const float* wp = wbase + dl * 80;
            float4 wa = *(const float4*)(wp + 0);
            float4 wb = *(const float4*)(wp + 4);
            float4 wc = *(const float4*)(wp + 8);
            float  wd = wp[12];
            cur1[0]  = fmaf(wa.x, xv, cur1[0]);
            cur1[1]  = fmaf(wa.y, xv, cur1[1]);
            cur1[2]  = fmaf(wa.z, xv, cur1[2]);
            cur1[3]  = fmaf(wa.w, xv, cur1[3]);
            cur1[4]  = fmaf(wb.x, xv, cur1[4]);
            cur1[5]  = fmaf(wb.y, xv, cur1[5]);
            cur1[6]  = fmaf(wb.z, xv, cur1[6]);
            cur1[7]  = fmaf(wb.w, xv, cur1[7]);
            cur1[8]  = fmaf(wc.x, xv, cur1[8]);
            cur1[9]  = fmaf(wc.y, xv, cur1[9]);
            cur1[10] = fmaf(wc.z, xv, cur1[10]);
            cur1[11] = fmaf(wc.w, xv, cur1[11]);
            cur1[12] = fmaf(wd,   xv, cur1[12]);
        }
    }
    // bias: separate rounded add (reference epilogue); pad h -> 0
#pragma unroll
    for (int i = 0; i < HP; ++i) {
        int h = hbase + i;
        cur1[i] = (h < H_HID) ? __fadd_rn(cur1[i], b1[h]) : 0.0f;
    }

    // ---- W2 columns register-resident ----
    float w2r[HP][C_OUT];
#pragma unroll
    for (int i = 0; i < HP; ++i) {
        float4 a = *(const float4*)&sW2[(hbase + i) * 8];
        w2r[i][0] = a.x; w2r[i][1] = a.y; w2r[i][2] = a.z; w2r[i][3] = a.w;
        w2r[i][4] = sW2[(hbase + i) * 8 + 4];
    }

    // ---- phase 2: pair-relay. Lane j handles pair p = i - j (t = 2p, 2p+1).
    // Each t's 50-term cur2 chain stays exactly serial across lanes (shfl
    // relay); the two timesteps inside a pair give 2x ILP on the serial
    // accumulation chains. Pad h never spikes (cur1=0, w2=0): exact no-ops.
    float mem1[HP];
#pragma unroll
    for (int i = 0; i < HP; ++i) mem1[i] = 0.0f;

    float P[2 * C_OUT];
#pragma unroll
    for (int c = 0; c < 2 * C_OUT; ++c) P[c] = 0.0f;

    float mem2[C_OUT], rb2[C_OUT];
#pragma unroll
    for (int c = 0; c < C_OUT; ++c) { mem2[c] = 0.0f; rb2[c] = b2[c]; }

    const size_t memoff = (size_t)steps * B * C_OUT;
    const int npairs = (steps + 1) >> 1;
    const int iters  = npairs + LPR - 1;
    const bool storer = (j == LPR - 1) && rowv;

    for (int i = 0; i < iters; ++i) {
        float q[2 * C_OUT];
#pragma unroll
        for (int c = 0; c < 2 * C_OUT; ++c)
            q[c] = __shfl_up_sync(0xFFFFFFFFu, P[c], 1, LPR);

        const int p = i - j;
        if ((unsigned)p < (unsigned)npairs) {
            float aA0 = (j == 0) ? 0.0f : q[0];
            float aA1 = (j == 0) ? 0.0f : q[1];
            float aA2 = (j == 0) ? 0.0f : q[2];
            float aA3 = (j == 0) ? 0.0f : q[3];
            float aA4 = (j == 0) ? 0.0f : q[4];
            float aB0 = (j == 0) ? 0.0f : q[5];
            float aB1 = (j == 0) ? 0.0f : q[6];
            float aB2 = (j == 0) ? 0.0f : q[7];
            float aB3 = (j == 0) ? 0.0f : q[8];
            float aB4 = (j == 0) ? 0.0f : q[9];

#pragma unroll
            for (int hh = 0; hh < HP; ++hh) {
                const float mo = mem1[hh];
                const float c1 = cur1[hh];
                const float r0 = (mo > THR) ? 1.0f : 0.0f;
                const float m1 = __fsub_rn(fmaf(BETA, mo, c1), r0);
                const float s1 = (m1 > THR) ? 1.0f : 0.0f;
                const float m2v = __fsub_rn(fmaf(BETA, m1, c1), s1);
                mem1[hh] = m2v;
                const float s2 = (m2v > THR) ? 1.0f : 0.0f;
                aA0 = fmaf(s1, w2r[hh][0], aA0);
                aA1 = fmaf(s1, w2r[hh][1], aA1);
                aA2 = fmaf(s1, w2r[hh][2], aA2);
                aA3 = fmaf(s1, w2r[hh][3], aA3);
                aA4 = fmaf(s1, w2r[hh][4], aA4);
                aB0 = fmaf(s2, w2r[hh][0], aB0);
                aB1 = fmaf(s2, w2r[hh][1], aB1);
                aB2 = fmaf(s2, w2r[hh][2], aB2);
                aB3 = fmaf(s2, w2r[hh][3], aB3);
                aB4 = fmaf(s2, w2r[hh][4], aB4);
            }
            P[0] = aA0; P[1] = aA1; P[2] = aA2; P[3] = aA3; P[4] = aA4;
            P[5] = aB0; P[6] = aB1; P[7] = aB2; P[8] = aB3; P[9] = aB4;

            if (storer) {
                const int t1 = 2 * p;
                const size_t ob1 = (size_t)t1 * B * C_OUT + (size_t)row * C_OUT;
#pragma unroll
                for (int c = 0; c < C_OUT; ++c) {
                    const float cur2 = __fadd_rn(P[c], rb2[c]);   // dot + b2
                    float m2 = mem2[c];
                    const float r2 = (m2 > THR) ? 1.0f : 0.0f;
                    m2 = __fsub_rn(fmaf(BETA, m2, cur2), r2);
                    mem2[c] = m2;
                    out[ob1 + c]          = (m2 > THR) ? 1.0f : 0.0f;
                    out[memoff + ob1 + c] = m2;
                }
                const int t2 = t1 + 1;
                if (t2 < steps) {
                    const size_t ob2 = ob1 + (size_t)B * C_OUT;
#pragma unroll
                    for (int c = 0; c < C_OUT; ++c) {
                        const float cur2 = __fadd_rn(P[5 + c], rb2[c]);
                        float m2 = mem2[c];
                        const float r2 = (m2 > THR) ? 1.0f : 0.0f;
                        m2 = __fsub_rn(fmaf(BETA, m2, cur2), r2);
                        mem2[c] = m2;
                        out[ob2 + c]          = (m2 > THR) ? 1.0f : 0.0f;
                        out[memoff + ob2 + c] = m2;
                    }
                }
            }
        }
    }
}

extern "C" void kernel_launch(void* const* d_in, const int* in_sizes, int n_in,
                              void* d_out, int out_size)
{
    const float* x  = (const float*)d_in[0];
    const float* W1 = (const float*)d_in[1];
    const float* b1 = (const float*)d_in[2];
    const float* W2 = (const float*)d_in[3];
    const float* b2 = (const float*)d_in[4];
    float* out = (float*)d_out;

    const int B = in_sizes[0] / D_IN;
    const int steps = (int)((long long)out_size / (2LL * B * C_OUT));

    cudaFuncSetAttribute(snn_fused_kernel,
                         cudaFuncAttributeMaxDynamicSharedMemorySize, SMEM_BYTES);

    const int grid = (B + RPB - 1) / RPB;
    snn_fused_kernel<<<grid, TPB, SMEM_BYTES>>>(x, W1, b1, W2, b2, out, B, steps);
}